// round 14
// baseline (speedup 1.0000x reference)
#include <cuda_runtime.h>
#include <cuda_bf16.h>
#include <math.h>

// B=32, L=1024, C=1024, E=64, TASKS=8, K=2
#define B_ 32
#define L_ 1024
#define C_ 1024
#define E_ 64
#define T_ 8
#define Y_ELEMS (B_ * L_ * C_)           // 33554432

#define CHUNKS 8                          // logit chunks per batch
#define LOGIT_BLOCKS (B_ * CHUNKS)        // 256 (8th finisher does gate inline)
#define ROWS_PER_BLOCK 8
#define SCALE_BLOCKS ((B_ * L_) / ROWS_PER_BLOCK)   // 4096
#define SCALE_BASE LOGIT_BLOCKS                      // 256
#define TOTAL_BLOCKS (SCALE_BASE + SCALE_BLOCKS)     // 4352

// Scratch (__device__ globals; allocation-free rule)
__device__ float d_partial[B_ * CHUNKS * E_];  // per-chunk partial logits
__device__ float d_s[B_ * L_];                 // combined gate scale per (b,l)
__device__ float d_tm[B_ * L_];                // per-batch token-mask contrib
__device__ float d_pm[B_ * E_];                // masked probs rows
__device__ int   d_lflag[B_];                  // per-batch chunk counters
__device__ int   d_bflag[B_];                  // per-batch gate-done flags
__device__ int   d_flag;                       // global gate-done counter
__device__ int   d_done;                       // completion counter (reset)

__device__ __forceinline__ int ld_acquire_gpu(const int* p) {
    int v;
    asm volatile("ld.acquire.gpu.b32 %0, [%1];" : "=r"(v) : "l"(p) : "memory");
    return v;
}
__device__ __forceinline__ void prefetch_l2(const void* p) {
    asm volatile("prefetch.global.L2 [%0];" :: "l"(p));
}
// Called by ONE thread per block, exactly once, after the block's last
// flag interaction. Last arriver resets all handshake state.
__device__ __forceinline__ void arrive_done() {
    int old = atomicAdd(&d_done, 1);
    if (old == TOTAL_BLOCKS - 1) {
#pragma unroll
        for (int b = 0; b < B_; b++) { d_lflag[b] = 0; d_bflag[b] = 0; }
        d_flag = 0;
        d_done = 0;
    }
}

__global__ __launch_bounds__(256, 5) void fused_kernel(
        const float4* __restrict__ x,
        const float*  __restrict__ x2,
        const float*  __restrict__ G,
        const float*  __restrict__ W1,
        const float*  __restrict__ b1,
        const float*  __restrict__ W2,
        float* __restrict__ out) {
    // Shared buffer aliased by branches (stage A needs 128+1024 floats).
    __shared__ __align__(16) float sh[1232];
    __shared__ int   last_sh;
    __shared__ float sg1_sh, sg2_sh, thresh_sh;
    __shared__ int   se1_sh, se2_sh;

    const int tid = threadIdx.x;
    const int blk = blockIdx.x;

    if (blk >= SCALE_BASE) {
        // ===================== SCALE (8 rows/block) =====================
        const int idx  = blk - SCALE_BASE;
        const int row0 = idx * ROWS_PER_BLOCK;
        const int batch = row0 >> 10;
        const size_t base = (size_t)row0 * 256 + tid;

        // 8 streaming loads in flight (32 KB/block) before the wait.
        float4 v0 = __ldcs(&x[base]);
        float4 v1 = __ldcs(&x[base + 256]);
        float4 v2 = __ldcs(&x[base + 512]);
        float4 v3 = __ldcs(&x[base + 768]);
        float4 v4 = __ldcs(&x[base + 1024]);
        float4 v5 = __ldcs(&x[base + 1280]);
        float4 v6 = __ldcs(&x[base + 1536]);
        float4 v7 = __ldcs(&x[base + 1792]);

        // Window-filling prefetches (free bandwidth during the gate wait):
        // idx<128: warm W2 (512 KB) for the logits stage.
        // idx in [128,384): warm all of G (8 MB) for the finisher + masks.
        if (idx < 128) {
            const float4* W2v = (const float4*)W2;
            prefetch_l2(&W2v[idx * 256 + tid]);
        } else if (idx < 384) {
            const char* Gb = (const char*)G;
            const size_t line = ((size_t)(idx - 128) * 256 + tid);
            prefetch_l2(Gb + line * 128);   // 65536 lines * 128B = 8 MB
        }

        // Wait only for this batch's gate publication.
        if (tid == 0) {
            while (ld_acquire_gpu(&d_bflag[batch]) == 0) __nanosleep(32);
        }
        __syncthreads();

        // Last flag interaction done -> arrive now (atomic hides under streaming).
        if (tid == 0 && idx != 0) arrive_done();

        const float s0 = d_s[row0 + 0];
        const float s1 = d_s[row0 + 1];
        const float s2 = d_s[row0 + 2];
        const float s3 = d_s[row0 + 3];
        const float s4 = d_s[row0 + 4];
        const float s5 = d_s[row0 + 5];
        const float s6 = d_s[row0 + 6];
        const float s7 = d_s[row0 + 7];

        v0.x *= s0; v0.y *= s0; v0.z *= s0; v0.w *= s0;
        v1.x *= s1; v1.y *= s1; v1.z *= s1; v1.w *= s1;
        v2.x *= s2; v2.y *= s2; v2.z *= s2; v2.w *= s2;
        v3.x *= s3; v3.y *= s3; v3.z *= s3; v3.w *= s3;
        v4.x *= s4; v4.y *= s4; v4.z *= s4; v4.w *= s4;
        v5.x *= s5; v5.y *= s5; v5.z *= s5; v5.w *= s5;
        v6.x *= s6; v6.y *= s6; v6.z *= s6; v6.w *= s6;
        v7.x *= s7; v7.y *= s7; v7.z *= s7; v7.w *= s7;

        float4* y = (float4*)out;
        __stcs(&y[base],        v0);
        __stcs(&y[base + 256],  v1);
        __stcs(&y[base + 512],  v2);
        __stcs(&y[base + 768],  v3);
        __stcs(&y[base + 1024], v4);
        __stcs(&y[base + 1280], v5);
        __stcs(&y[base + 1536], v6);
        __stcs(&y[base + 1792], v7);

        // First scale block: masks (needs ALL batches; off critical path).
        // Layout: [y (32M), expert_mask (64), token_mask (1024)]
        if (idx == 0) {
            if (tid == 0) {
                while (ld_acquire_gpu(&d_flag) < B_) __nanosleep(64);
            }
            __syncthreads();
#pragma unroll
            for (int j = 0; j < 4; j++) {
                int l = tid + j * 256;
                float tm = 0.0f;
#pragma unroll
                for (int b = 0; b < B_; b++) tm += d_tm[b * L_ + l];
                out[Y_ELEMS + E_ + l] = tm;
            }
            if (tid < E_) {
                float em = 0.0f;
#pragma unroll
                for (int b = 0; b < B_; b++) em += d_pm[b * E_ + tid];
                out[Y_ELEMS + tid] = em;
            }
            __syncthreads();
            if (tid == 0) arrive_done();
        }
    } else {
        // ============ GATING: 8 chunk blocks per batch; 8th finishes ============
        const int b  = blk >> 3;         // batch
        const int ch = blk & 7;          // chunk of 128 c's
        float* hg   = sh;                // 128 floats
        float* part = sh + 128;          // 16*64 floats

        // Preload this thread's 8 W2 vectors BEFORE the hgate barrier —
        // independent of hg, overlaps W2 DRAM latency with hgate compute.
        const int eg    = tid & 15;
        const int csub  = tid >> 4;
        const int cbase = ch * 128 + csub * 8;
        const float4* W2v = (const float4*)W2;  // row = 32 float4
        const float4 w0 = __ldg(&W2v[(cbase + 0) * 32 + eg]);
        const float4 w1 = __ldg(&W2v[(cbase + 1) * 32 + eg]);
        const float4 w2 = __ldg(&W2v[(cbase + 2) * 32 + eg]);
        const float4 w3 = __ldg(&W2v[(cbase + 3) * 32 + eg]);
        const float4 w4 = __ldg(&W2v[(cbase + 4) * 32 + eg]);
        const float4 w5 = __ldg(&W2v[(cbase + 5) * 32 + eg]);
        const float4 w6 = __ldg(&W2v[(cbase + 6) * 32 + eg]);
        const float4 w7 = __ldg(&W2v[(cbase + 7) * 32 + eg]);

        if (tid < 128) {
            const int c = ch * 128 + tid;
            float xr[T_];
#pragma unroll
            for (int t = 0; t < T_; t++) xr[t] = x2[b * T_ + t];
            float h = b1[c];
#pragma unroll
            for (int t = 0; t < T_; t++) h = fmaf(xr[t], W1[t * C_ + c], h);
            h = 0.5f * h * (1.0f + erff(h * 0.70710678118654752f));
            hg[tid] = h;
        }
        __syncthreads();

        // partial logits: 4 experts x 8 c's with preloaded W2.
        {
            const float* hl = &hg[csub * 8];
            float4 acc = make_float4(0.f, 0.f, 0.f, 0.f);
            float h;
            h = hl[0]; acc.x = fmaf(h, w0.x, acc.x); acc.y = fmaf(h, w0.y, acc.y);
                       acc.z = fmaf(h, w0.z, acc.z); acc.w = fmaf(h, w0.w, acc.w);
            h = hl[1]; acc.x = fmaf(h, w1.x, acc.x); acc.y = fmaf(h, w1.y, acc.y);
                       acc.z = fmaf(h, w1.z, acc.z); acc.w = fmaf(h, w1.w, acc.w);
            h = hl[2]; acc.x = fmaf(h, w2.x, acc.x); acc.y = fmaf(h, w2.y, acc.y);
                       acc.z = fmaf(h, w2.z, acc.z); acc.w = fmaf(h, w2.w, acc.w);
            h = hl[3]; acc.x = fmaf(h, w3.x, acc.x); acc.y = fmaf(h, w3.y, acc.y);
                       acc.z = fmaf(h, w3.z, acc.z); acc.w = fmaf(h, w3.w, acc.w);
            h = hl[4]; acc.x = fmaf(h, w4.x, acc.x); acc.y = fmaf(h, w4.y, acc.y);
                       acc.z = fmaf(h, w4.z, acc.z); acc.w = fmaf(h, w4.w, acc.w);
            h = hl[5]; acc.x = fmaf(h, w5.x, acc.x); acc.y = fmaf(h, w5.y, acc.y);
                       acc.z = fmaf(h, w5.z, acc.z); acc.w = fmaf(h, w5.w, acc.w);
            h = hl[6]; acc.x = fmaf(h, w6.x, acc.x); acc.y = fmaf(h, w6.y, acc.y);
                       acc.z = fmaf(h, w6.z, acc.z); acc.w = fmaf(h, w6.w, acc.w);
            h = hl[7]; acc.x = fmaf(h, w7.x, acc.x); acc.y = fmaf(h, w7.y, acc.y);
                       acc.z = fmaf(h, w7.z, acc.z); acc.w = fmaf(h, w7.w, acc.w);
            float* p = &part[csub * 64 + eg * 4];
            p[0] = acc.x; p[1] = acc.y; p[2] = acc.z; p[3] = acc.w;
        }
        __syncthreads();

        if (tid < E_) {
            float acc = 0.0f;
#pragma unroll
            for (int cs = 0; cs < 16; cs++) acc += part[cs * 64 + tid];
            d_partial[(b * CHUNKS + ch) * E_ + tid] = acc;
        }
        __syncthreads();
        if (tid == 0) {
            __threadfence();
            last_sh = (atomicAdd(&d_lflag[b], 1) == CHUNKS - 1) ? 1 : 0;
        }
        __syncthreads();

        if (!last_sh) {
            if (tid == 0) arrive_done();   // non-finisher: no more flag use
        } else {
            // ---- This block is the 8th arriver: finish the gate inline ----
            __threadfence();   // acquire side: make peers' partials visible
            float* probs_sh = sh;
            if (tid < E_) {
                float acc = 0.0f;
#pragma unroll
                for (int c2 = 0; c2 < CHUNKS; c2++)
                    acc += d_partial[(b * CHUNKS + c2) * E_ + tid];
                probs_sh[tid] = acc;   // logits
            }
            __syncthreads();

            // warp 0: softmax + top-2 via shuffles
            if (tid < 32) {
                const float la = probs_sh[tid];
                const float lb = probs_sh[tid + 32];

                float m = fmaxf(la, lb);
#pragma unroll
                for (int off = 16; off > 0; off >>= 1)
                    m = fmaxf(m, __shfl_xor_sync(0xffffffffu, m, off));

                float ea = expf(la - m);
                float eb = expf(lb - m);
                float s = ea + eb;
#pragma unroll
                for (int off = 16; off > 0; off >>= 1)
                    s += __shfl_xor_sync(0xffffffffu, s, off);
                const float inv = 1.0f / s;

                float pa = fmaf(ea, inv, 0.0001f);
                float pb = fmaf(eb, inv, 0.0001f);
                probs_sh[tid]      = pa;
                probs_sh[tid + 32] = pb;

                float t1, t2; int i1, i2;
                if (pa >= pb) { t1 = pa; i1 = tid;      t2 = pb; i2 = tid + 32; }
                else          { t1 = pb; i1 = tid + 32; t2 = pa; i2 = tid; }
#pragma unroll
                for (int off = 16; off > 0; off >>= 1) {
                    float o1 = __shfl_xor_sync(0xffffffffu, t1, off);
                    int  oi1 = __shfl_xor_sync(0xffffffffu, i1, off);
                    float o2 = __shfl_xor_sync(0xffffffffu, t2, off);
                    int  oi2 = __shfl_xor_sync(0xffffffffu, i2, off);
                    if (o1 > t1) {
                        if (t1 > o2) { t2 = t1; i2 = i1; }
                        else         { t2 = o2; i2 = oi2; }
                        t1 = o1; i1 = oi1;
                    } else if (o1 > t2) {
                        t2 = o1; i2 = oi1;
                    }
                }
                if (tid == 0) {
                    se1_sh = i1; se2_sh = i2;
                    sg1_sh = t1; sg2_sh = t2;
                    thresh_sh = t2;
                }
            }
            __syncthreads();

            if (tid < E_) {
                const float p = probs_sh[tid];
                d_pm[b * E_ + tid] = (p >= thresh_sh) ? p : 0.0f;
            }

            // per-(b,l) scale + token-mask contribution; 4 l's per thread
#pragma unroll
            for (int j = 0; j < 4; j++) {
                const int l = tid + j * 256;
                const float ga = G[((size_t)(b * E_ + se1_sh) << 10) + l];
                const float gb = G[((size_t)(b * E_ + se2_sh) << 10) + l];
                d_s[b * L_ + l]  = fmaf(sg1_sh, ga, sg2_sh * gb);
                d_tm[b * L_ + l] = ga + gb;
            }

            __syncthreads();
            if (tid == 0) {
                __threadfence();
                d_bflag[b] = 1;          // per-batch release
                atomicAdd(&d_flag, 1);   // global counter for the masks block
                arrive_done();
            }
        }
    }
}

extern "C" void kernel_launch(void* const* d_in, const int* in_sizes, int n_in,
                              void* d_out, int out_size) {
    const float* x  = (const float*)d_in[0];  // input_features (32,1024,1024)
    const float* x2 = (const float*)d_in[1];  // input_features2 (32,8)
    const float* G  = (const float*)d_in[2];  // G (32,64,1024)
    const float* W1 = (const float*)d_in[3];  // W1 (8,1024)
    const float* b1 = (const float*)d_in[4];  // b1 (1024,)
    const float* W2 = (const float*)d_in[5];  // W2 (1024,128)
    float* out = (float*)d_out;

    fused_kernel<<<TOTAL_BLOCKS, 256>>>((const float4*)x, x2, G, W1, b1, W2, out);
}

// round 15
// speedup vs baseline: 1.0434x; 1.0434x over previous
#include <cuda_runtime.h>
#include <cuda_bf16.h>
#include <math.h>

// B=32, L=1024, C=1024, E=64, TASKS=8, K=2
#define B_ 32
#define L_ 1024
#define C_ 1024
#define E_ 64
#define T_ 8
#define Y_ELEMS (B_ * L_ * C_)           // 33554432

#define CHUNKS 8                          // logit chunks per batch
#define LOGIT_BLOCKS (B_ * CHUNKS)        // 256 (8th finisher does gate inline)
#define ROWS_PER_BLOCK 8
#define SCALE_BLOCKS ((B_ * L_) / ROWS_PER_BLOCK)   // 4096
#define SCALE_BASE LOGIT_BLOCKS                      // 256
#define TOTAL_BLOCKS (SCALE_BASE + SCALE_BLOCKS)     // 4352
#define PF_AHEAD 1024                      // tiles ahead for L2 x-prefetch

// Scratch (__device__ globals; allocation-free rule)
__device__ float d_partial[B_ * CHUNKS * E_];  // per-chunk partial logits
__device__ float d_s[B_ * L_];                 // combined gate scale per (b,l)
__device__ float d_tm[B_ * L_];                // per-batch token-mask contrib
__device__ float d_pm[B_ * E_];                // masked probs rows
__device__ int   d_lflag[B_];                  // per-batch chunk counters
__device__ int   d_bflag[B_];                  // per-batch gate-done flags
__device__ int   d_flag;                       // global gate-done counter
__device__ int   d_done;                       // completion counter (reset)

__device__ __forceinline__ int ld_acquire_gpu(const int* p) {
    int v;
    asm volatile("ld.acquire.gpu.b32 %0, [%1];" : "=r"(v) : "l"(p) : "memory");
    return v;
}
__device__ __forceinline__ void prefetch_l2(const void* p) {
    asm volatile("prefetch.global.L2 [%0];" :: "l"(p));
}

__global__ __launch_bounds__(256) void fused_kernel(
        const float4* __restrict__ x,
        const float*  __restrict__ x2,
        const float*  __restrict__ G,
        const float*  __restrict__ W1,
        const float*  __restrict__ b1,
        const float*  __restrict__ W2,
        float* __restrict__ out) {
    // Shared buffer aliased by branches (stage A needs 128+1024 floats).
    __shared__ __align__(16) float sh[1232];
    __shared__ int   last_sh;
    __shared__ float sg1_sh, sg2_sh, thresh_sh;
    __shared__ int   se1_sh, se2_sh;

    const int tid = threadIdx.x;
    const int blk = blockIdx.x;

    if (blk >= SCALE_BASE) {
        // ===================== SCALE (8 rows/block) =====================
        const int idx  = blk - SCALE_BASE;
        const int row0 = idx * ROWS_PER_BLOCK;
        const int batch = row0 >> 10;
        const size_t base = (size_t)row0 * 256 + tid;

        // 8 streaming loads in flight (32 KB/block) before the wait.
        float4 v0 = __ldcs(&x[base]);
        float4 v1 = __ldcs(&x[base + 256]);
        float4 v2 = __ldcs(&x[base + 512]);
        float4 v3 = __ldcs(&x[base + 768]);
        float4 v4 = __ldcs(&x[base + 1024]);
        float4 v5 = __ldcs(&x[base + 1280]);
        float4 v6 = __ldcs(&x[base + 1536]);
        float4 v7 = __ldcs(&x[base + 1792]);

        // Fill the gate window with USEFUL reads:
        // idx<128: warm W2 (512 KB) for the logits stage.
        // idx<PF_AHEAD: pull tile (idx+PF_AHEAD)'s x data (32 KB) into L2.
        //   Bounded 32 MB total, consumed by waves 2-3 within ~10 us ->
        //   no duplicate DRAM reads, just reordered into the dead window.
        if (idx < 128) {
            const float4* W2v = (const float4*)W2;
            prefetch_l2(&W2v[idx * 256 + tid]);
        }
        if (idx < PF_AHEAD) {
            const char* xp = (const char*)x
                           + (size_t)(idx + PF_AHEAD) * (ROWS_PER_BLOCK * 4096)
                           + (size_t)tid * 128;
            prefetch_l2(xp);
        }

        // Wait only for this batch's gate publication.
        if (tid == 0) {
            while (ld_acquire_gpu(&d_bflag[batch]) == 0) __nanosleep(32);
        }
        __syncthreads();

        const float s0 = d_s[row0 + 0];
        const float s1 = d_s[row0 + 1];
        const float s2 = d_s[row0 + 2];
        const float s3 = d_s[row0 + 3];
        const float s4 = d_s[row0 + 4];
        const float s5 = d_s[row0 + 5];
        const float s6 = d_s[row0 + 6];
        const float s7 = d_s[row0 + 7];

        v0.x *= s0; v0.y *= s0; v0.z *= s0; v0.w *= s0;
        v1.x *= s1; v1.y *= s1; v1.z *= s1; v1.w *= s1;
        v2.x *= s2; v2.y *= s2; v2.z *= s2; v2.w *= s2;
        v3.x *= s3; v3.y *= s3; v3.z *= s3; v3.w *= s3;
        v4.x *= s4; v4.y *= s4; v4.z *= s4; v4.w *= s4;
        v5.x *= s5; v5.y *= s5; v5.z *= s5; v5.w *= s5;
        v6.x *= s6; v6.y *= s6; v6.z *= s6; v6.w *= s6;
        v7.x *= s7; v7.y *= s7; v7.z *= s7; v7.w *= s7;

        float4* y = (float4*)out;
        __stcs(&y[base],        v0);
        __stcs(&y[base + 256],  v1);
        __stcs(&y[base + 512],  v2);
        __stcs(&y[base + 768],  v3);
        __stcs(&y[base + 1024], v4);
        __stcs(&y[base + 1280], v5);
        __stcs(&y[base + 1536], v6);
        __stcs(&y[base + 1792], v7);

        // First scale block: masks (needs ALL batches; off critical path).
        // Layout: [y (32M), expert_mask (64), token_mask (1024)]
        if (idx == 0) {
            if (tid == 0) {
                while (ld_acquire_gpu(&d_flag) < B_) __nanosleep(64);
            }
            __syncthreads();
#pragma unroll
            for (int j = 0; j < 4; j++) {
                int l = tid + j * 256;
                float tm = 0.0f;
#pragma unroll
                for (int b = 0; b < B_; b++) tm += d_tm[b * L_ + l];
                out[Y_ELEMS + E_ + l] = tm;
            }
            if (tid < E_) {
                float em = 0.0f;
#pragma unroll
                for (int b = 0; b < B_; b++) em += d_pm[b * E_ + tid];
                out[Y_ELEMS + tid] = em;
            }
        }
    } else {
        // ============ GATING: 8 chunk blocks per batch; 8th finishes ============
        const int b  = blk >> 3;         // batch
        const int ch = blk & 7;          // chunk of 128 c's
        float* hg   = sh;                // 128 floats
        float* part = sh + 128;          // 16*64 floats

        if (tid < 128) {
            const int c = ch * 128 + tid;
            float xr[T_];
#pragma unroll
            for (int t = 0; t < T_; t++) xr[t] = x2[b * T_ + t];
            float h = b1[c];
#pragma unroll
            for (int t = 0; t < T_; t++) h = fmaf(xr[t], W1[t * C_ + c], h);
            h = 0.5f * h * (1.0f + erff(h * 0.70710678118654752f));
            hg[tid] = h;
        }
        __syncthreads();

        // partial logits: eg = tid&15 (experts 4eg..4eg+3), csub = tid>>4
        {
            const int eg   = tid & 15;
            const int csub = tid >> 4;
            const float4* W2v = (const float4*)W2;  // row = 32 float4
            float4 acc = make_float4(0.f, 0.f, 0.f, 0.f);
#pragma unroll
            for (int j = 0; j < 8; j++) {
                const int cl = csub * 8 + j;
                const int c  = ch * 128 + cl;
                const float h = hg[cl];
                const float4 w = __ldg(&W2v[c * 32 + eg]);
                acc.x = fmaf(h, w.x, acc.x);
                acc.y = fmaf(h, w.y, acc.y);
                acc.z = fmaf(h, w.z, acc.z);
                acc.w = fmaf(h, w.w, acc.w);
            }
            float* p = &part[csub * 64 + eg * 4];
            p[0] = acc.x; p[1] = acc.y; p[2] = acc.z; p[3] = acc.w;
        }
        __syncthreads();

        if (tid < E_) {
            float acc = 0.0f;
#pragma unroll
            for (int cs = 0; cs < 16; cs++) acc += part[cs * 64 + tid];
            d_partial[(b * CHUNKS + ch) * E_ + tid] = acc;
        }
        __syncthreads();
        if (tid == 0) {
            __threadfence();
            last_sh = (atomicAdd(&d_lflag[b], 1) == CHUNKS - 1) ? 1 : 0;
        }
        __syncthreads();

        if (last_sh) {
            // ---- This block is the 8th arriver: finish the gate inline ----
            __threadfence();   // acquire side: make peers' partials visible
            float* probs_sh = sh;
            if (tid < E_) {
                float acc = 0.0f;
#pragma unroll
                for (int c2 = 0; c2 < CHUNKS; c2++)
                    acc += d_partial[(b * CHUNKS + c2) * E_ + tid];
                probs_sh[tid] = acc;   // logits
            }
            __syncthreads();

            // warp 0: softmax + top-2 via shuffles
            if (tid < 32) {
                const float la = probs_sh[tid];
                const float lb = probs_sh[tid + 32];

                float m = fmaxf(la, lb);
#pragma unroll
                for (int off = 16; off > 0; off >>= 1)
                    m = fmaxf(m, __shfl_xor_sync(0xffffffffu, m, off));

                float ea = expf(la - m);
                float eb = expf(lb - m);
                float s = ea + eb;
#pragma unroll
                for (int off = 16; off > 0; off >>= 1)
                    s += __shfl_xor_sync(0xffffffffu, s, off);
                const float inv = 1.0f / s;

                float pa = fmaf(ea, inv, 0.0001f);
                float pb = fmaf(eb, inv, 0.0001f);
                probs_sh[tid]      = pa;
                probs_sh[tid + 32] = pb;

                float t1, t2; int i1, i2;
                if (pa >= pb) { t1 = pa; i1 = tid;      t2 = pb; i2 = tid + 32; }
                else          { t1 = pb; i1 = tid + 32; t2 = pa; i2 = tid; }
#pragma unroll
                for (int off = 16; off > 0; off >>= 1) {
                    float o1 = __shfl_xor_sync(0xffffffffu, t1, off);
                    int  oi1 = __shfl_xor_sync(0xffffffffu, i1, off);
                    float o2 = __shfl_xor_sync(0xffffffffu, t2, off);
                    int  oi2 = __shfl_xor_sync(0xffffffffu, i2, off);
                    if (o1 > t1) {
                        if (t1 > o2) { t2 = t1; i2 = i1; }
                        else         { t2 = o2; i2 = oi2; }
                        t1 = o1; i1 = oi1;
                    } else if (o1 > t2) {
                        t2 = o1; i2 = oi1;
                    }
                }
                if (tid == 0) {
                    se1_sh = i1; se2_sh = i2;
                    sg1_sh = t1; sg2_sh = t2;
                    thresh_sh = t2;
                }
            }
            __syncthreads();

            if (tid < E_) {
                const float p = probs_sh[tid];
                d_pm[b * E_ + tid] = (p >= thresh_sh) ? p : 0.0f;
            }

            // per-(b,l) scale + token-mask contribution; 4 l's per thread
#pragma unroll
            for (int j = 0; j < 4; j++) {
                const int l = tid + j * 256;
                const float ga = G[((size_t)(b * E_ + se1_sh) << 10) + l];
                const float gb = G[((size_t)(b * E_ + se2_sh) << 10) + l];
                d_s[b * L_ + l]  = fmaf(sg1_sh, ga, sg2_sh * gb);
                d_tm[b * L_ + l] = ga + gb;
            }

            __syncthreads();
            if (tid == 0) {
                __threadfence();
                d_bflag[b] = 1;          // per-batch release
                atomicAdd(&d_flag, 1);   // global counter for the masks block
            }
        }
    }

    // -------- reset handshake state for next graph replay --------
    __syncthreads();
    if (tid == 0) {
        int old = atomicAdd(&d_done, 1);
        if (old == TOTAL_BLOCKS - 1) {
#pragma unroll
            for (int b = 0; b < B_; b++) { d_lflag[b] = 0; d_bflag[b] = 0; }
            d_flag = 0;
            d_done = 0;
        }
    }
}

extern "C" void kernel_launch(void* const* d_in, const int* in_sizes, int n_in,
                              void* d_out, int out_size) {
    const float* x  = (const float*)d_in[0];  // input_features (32,1024,1024)
    const float* x2 = (const float*)d_in[1];  // input_features2 (32,8)
    const float* G  = (const float*)d_in[2];  // G (32,64,1024)
    const float* W1 = (const float*)d_in[3];  // W1 (8,1024)
    const float* b1 = (const float*)d_in[4];  // b1 (1024,)
    const float* W2 = (const float*)d_in[5];  // W2 (1024,128)
    float* out = (float*)d_out;

    fused_kernel<<<TOTAL_BLOCKS, 256>>>((const float4*)x, x2, G, W1, b1, W2, out);
}